// round 8
// baseline (speedup 1.0000x reference)
#include <cuda_runtime.h>
#include <stdint.h>
#include <math.h>

// Problem constants (fixed by the dataset).
#define NN      8192
#define CC      64
#define EMAX    262144
#define PAD     128                 // padded CSR row stride (mean deg 32)
#define TS      (1u << 19)          // hash slots (load factor ~0.5)
#define TMASK   (TS - 1u)
#define LISTCAP 16384

#define NBLK    296                 // 2 blocks/SM on 148 SMs (GB300 has 152)
#define NTHR    512
#define NT      (NBLK * NTHR)       // 151552 threads
#define NWARP   (NT / 32)           // 4736 warps

// ---------------- scratch (static device globals; no allocation) -------------
__device__ __align__(16) unsigned long long g_table[TS];   // 4 MB dedupe hash
__device__ unsigned g_pos[TS];            // apos recorded by the claimant of a slot
__device__ int      g_count[NN];
__device__ float    g_deg[NN];
__device__ float    g_dinv[NN];
__device__ __align__(16) uint2 g_cw[NN * PAD];   // 8 MB interleaved (col, w)
__device__ float2   g_tx1[NN * 32];
__device__ float2   g_ltx1[NN * 32];
__device__ int      g_nlist;
__device__ uint2    g_list[LISTCAP];      // (slot, edge idx) of duplicate-key inserts
__device__ int      g_is64;

// Grid-wide sense-reversing barrier (all NBLK blocks are co-resident by
// construction: launch_bounds(512,2), 0 smem, 296 <= 2*148 blocks).
__device__ volatile unsigned g_gen;
__device__ unsigned          g_cnt;

__device__ __forceinline__ void gsync() {
    __syncthreads();
    if (threadIdx.x == 0) {
        __threadfence();
        unsigned gen = g_gen;
        if (atomicAdd(&g_cnt, 1u) == NBLK - 1) {
            g_cnt = 0;
            __threadfence();
            g_gen = gen + 1u;
        } else {
            while (g_gen == gen) { }
        }
        __threadfence();
    }
    __syncthreads();
}

// ---------------- the one kernel ---------------------------------------------

__global__ void __launch_bounds__(NTHR, 2)
mega(const float* __restrict__ x,
     const unsigned* __restrict__ ei,     // int32 OR int64 raw words
     const float* __restrict__ ew,
     const float* __restrict__ W,
     const float* __restrict__ adw,
     const float* __restrict__ bias,
     float* __restrict__ out, int E) {
    const int tid  = blockIdx.x * NTHR + threadIdx.x;
    const int lane = threadIdx.x & 31;
    const int gw   = tid >> 5;                       // global warp id
    const float2* __restrict__ X2 = (const float2*)x;

    // ---- P0: clear table + counters; detect edge dtype ----------------------
    {
        ulonglong2 z = make_ulonglong2(0ull, 0ull);
        for (unsigned i = tid; i < TS / 2; i += NT) ((ulonglong2*)g_table)[i] = z;
        if (tid < NN) { g_count[tid] = 0; g_deg[tid] = 0.f; }
        if (tid == 0) {
            g_nlist = 0;
            int all_zero = 1;
            for (int j = 1; j < 64; j += 2) all_zero &= (ei[j] == 0u);
            g_is64 = all_zero;   // int64 LE with values<2^31 => odd words zero
        }
    }
    gsync();

    // ---- P1: hash insert -----------------------------------------------------
    {
        const int is64 = g_is64;
        const float sig = 1.f / (1.f + expf(-adw[0]));
        for (int i = tid; i < E; i += NT) {
            unsigned row = is64 ? ei[2 * i]       : ei[i];
            unsigned col = is64 ? ei[2 * (E + i)] : ei[E + i];
            float aw  = ew[i] * sig;
            unsigned key = (row << 13) | col;                 // < 2^26
            unsigned long long packed =
                ((unsigned long long)(key + 1u) << 32) | (unsigned)(i + 1);
            unsigned slot = ((key * 2654435761u) >> 12) & TMASK;
            while (true) {
                unsigned long long cur = g_table[slot];
                if (cur == 0ull) {
                    unsigned long long old = atomicCAS(&g_table[slot], 0ull, packed);
                    if (old == 0ull) {                         // claimed this cell
                        int pos = atomicAdd(&g_count[row], 1);
                        if (pos < PAD) {
                            unsigned apos = (row << 7) + (unsigned)pos;
                            g_pos[slot] = apos;
                            g_cw[apos]  = make_uint2(col, __float_as_uint(aw));
                            atomicAdd(&g_deg[row], aw);        // REDG (no return)
                        }
                        break;
                    }
                    cur = old;
                }
                if ((cur >> 32) == (unsigned long long)(key + 1u)) {  // dup cell
                    atomicMax(&g_table[slot], packed);         // max idx = last write wins
                    int p = atomicAdd(&g_nlist, 1);
                    if (p < LISTCAP) g_list[p] = make_uint2(slot, (unsigned)i);
                    break;
                }
                slot = (slot + 1u) & TMASK;
            }
        }
    }
    gsync();

    // ---- P2: last-write-wins corrections for duplicate cells (few hundred) ---
    {
        const float sig = 1.f / (1.f + expf(-adw[0]));
        int n = g_nlist; if (n > LISTCAP) n = LISTCAP;
        for (int idx = tid; idx < n; idx += NT) {
            unsigned slot = g_list[idx].x;
            unsigned i    = g_list[idx].y;
            unsigned long long cur = g_table[slot];
            if ((unsigned)cur != i + 1u) continue;             // not the winner
            unsigned apos = g_pos[slot];
            float aw  = ew[i] * sig;
            float old = __uint_as_float(g_cw[apos].y);
            g_cw[apos].y = __float_as_uint(aw);
            atomicAdd(&g_deg[apos >> 7], aw - old);
        }
    }
    gsync();

    // ---- P3: dinv + fold dinv[col] into CSR weights --------------------------
    {
        for (int row = gw; row < NN; row += NWARP) {
            int cnt = g_count[row]; if (cnt > PAD) cnt = PAD;
            int base = row << 7;
            for (int j = lane; j < cnt; j += 32) {
                uint2 cw = g_cw[base + j];
                float w = __uint_as_float(cw.y) * rsqrtf(g_deg[cw.x] + 1.0f);
                g_cw[base + j].y = __float_as_uint(w);
            }
        }
        if (tid < NN) g_dinv[tid] = rsqrtf(g_deg[tid] + 1.0f);
    }
    gsync();

    // ---- P4: Tx1 = L x --------------------------------------------------------
    for (int row = gw; row < NN; row += NWARP) {
        int cnt = g_count[row]; if (cnt > PAD) cnt = PAD;
        const uint4* __restrict__ cw4 = (const uint4*)(g_cw + (row << 7));
        float ax = 0.f, ay = 0.f;
        for (int j = 0; j < cnt; j += 32) {                    // zero-padded chunks
            const uint4* p = cw4 + (j >> 1);
#pragma unroll
            for (int t = 0; t < 16; t++) {                     // 2 edges per load
                uint4 e = p[t];                                // uniform broadcast
                float2 v0 = X2[e.x * 32 + lane];
                float2 v1 = X2[e.z * 32 + lane];
                float w0 = __uint_as_float(e.y), w1 = __uint_as_float(e.w);
                ax = fmaf(w0, v0.x, ax);  ay = fmaf(w0, v0.y, ay);
                ax = fmaf(w1, v1.x, ax);  ay = fmaf(w1, v1.y, ay);
            }
        }
        float di = g_dinv[row];
        float2 xo = X2[row * 32 + lane];
        g_tx1[row * 32 + lane] =
            make_float2(xo.x - di * (ax + di * xo.x),
                        xo.y - di * (ay + di * xo.y));
    }
    gsync();

    // ---- P5: LTx1 = L Tx1 -----------------------------------------------------
    for (int row = gw; row < NN; row += NWARP) {
        int cnt = g_count[row]; if (cnt > PAD) cnt = PAD;
        const uint4* __restrict__ cw4 = (const uint4*)(g_cw + (row << 7));
        float ax = 0.f, ay = 0.f;
        for (int j = 0; j < cnt; j += 32) {
            const uint4* p = cw4 + (j >> 1);
#pragma unroll
            for (int t = 0; t < 16; t++) {
                uint4 e = p[t];
                float2 v0 = g_tx1[e.x * 32 + lane];
                float2 v1 = g_tx1[e.z * 32 + lane];
                float w0 = __uint_as_float(e.y), w1 = __uint_as_float(e.w);
                ax = fmaf(w0, v0.x, ax);  ay = fmaf(w0, v0.y, ay);
                ax = fmaf(w1, v1.x, ax);  ay = fmaf(w1, v1.y, ay);
            }
        }
        float di = g_dinv[row];
        float2 t1 = g_tx1[row * 32 + lane];
        g_ltx1[row * 32 + lane] =
            make_float2(t1.x - di * (ax + di * t1.x),
                        t1.y - di * (ay + di * t1.y));
    }
    gsync();

    // ---- P6: out = x*W0 + Tx1*W1 + (2*LTx1 - x)*W2 + bias --------------------
    // 4 rows per warp; groups spread round-robin across blocks so all SMs work.
    {
        int wib = threadIdx.x >> 5;
        int grp = wib * NBLK + blockIdx.x;                     // < 16*296 = 4736
        if (grp < NN / 4) {
            int row0 = grp * 4;
            const float2* __restrict__ W2 = (const float2*)W;  // L1-resident 48 KB
            float2* __restrict__ O2 = (float2*)out;

            float2 xv[4], t1[4], t2[4], acc[4];
#pragma unroll
            for (int r = 0; r < 4; r++) {
                int row = row0 + r;
                xv[r] = X2[row * 32 + lane];
                t1[r] = g_tx1[row * 32 + lane];
                float2 lv = g_ltx1[row * 32 + lane];
                t2[r].x = 2.f * lv.x - xv[r].x;
                t2[r].y = 2.f * lv.y - xv[r].y;
                acc[r].x = 0.f; acc[r].y = 0.f;
            }
#pragma unroll 8
            for (int kp = 0; kp < 32; kp++) {
                int k0 = 2 * kp, k1 = 2 * kp + 1;
                float2 w00 = W2[k0 * 32 + lane],        w01 = W2[k1 * 32 + lane];
                float2 w10 = W2[2048 + k0 * 32 + lane], w11 = W2[2048 + k1 * 32 + lane];
                float2 w20 = W2[4096 + k0 * 32 + lane], w21 = W2[4096 + k1 * 32 + lane];
#pragma unroll
                for (int r = 0; r < 4; r++) {
                    float bx0 = __shfl_sync(0xffffffffu, xv[r].x, kp);
                    float bx1 = __shfl_sync(0xffffffffu, xv[r].y, kp);
                    float b10 = __shfl_sync(0xffffffffu, t1[r].x, kp);
                    float b11 = __shfl_sync(0xffffffffu, t1[r].y, kp);
                    float b20 = __shfl_sync(0xffffffffu, t2[r].x, kp);
                    float b21 = __shfl_sync(0xffffffffu, t2[r].y, kp);
                    acc[r].x = fmaf(bx0, w00.x, acc[r].x); acc[r].x = fmaf(bx1, w01.x, acc[r].x);
                    acc[r].x = fmaf(b10, w10.x, acc[r].x); acc[r].x = fmaf(b11, w11.x, acc[r].x);
                    acc[r].x = fmaf(b20, w20.x, acc[r].x); acc[r].x = fmaf(b21, w21.x, acc[r].x);
                    acc[r].y = fmaf(bx0, w00.y, acc[r].y); acc[r].y = fmaf(bx1, w01.y, acc[r].y);
                    acc[r].y = fmaf(b10, w10.y, acc[r].y); acc[r].y = fmaf(b11, w11.y, acc[r].y);
                    acc[r].y = fmaf(b20, w20.y, acc[r].y); acc[r].y = fmaf(b21, w21.y, acc[r].y);
                }
            }
            float2 b2 = ((const float2*)bias)[lane];
#pragma unroll
            for (int r = 0; r < 4; r++)
                O2[(row0 + r) * 32 + lane] = make_float2(acc[r].x + b2.x, acc[r].y + b2.y);
        }
    }
}

// ---------------- launch -----------------------------------------------------

extern "C" void kernel_launch(void* const* d_in, const int* in_sizes, int n_in,
                              void* d_out, int out_size) {
    const float*    x    = (const float*)d_in[0];
    const unsigned* ei   = (const unsigned*)d_in[1];
    const float*    ew   = (const float*)d_in[2];
    const float*    W    = (const float*)d_in[3];
    const float*    adw  = (const float*)d_in[4];
    const float*    bias = (const float*)d_in[5];
    float*          out  = (float*)d_out;

    int E = in_sizes[2];
    if (E > EMAX) E = EMAX;

    mega<<<NBLK, NTHR>>>(x, ei, ew, W, adw, bias, out, E);
}

// round 9
// speedup vs baseline: 1.0329x; 1.0329x over previous
#include <cuda_runtime.h>
#include <stdint.h>
#include <math.h>

// Problem constants (fixed by the dataset).
#define NN      8192
#define CC      64
#define EMAX    262144
#define PAD     128                 // padded CSR row stride (mean deg 32)
#define TS      (1u << 19)          // hash slots (load factor ~0.5)
#define TMASK   (TS - 1u)
#define LISTCAP 16384

// ---------------- scratch (static device globals; no allocation) -------------
__device__ __align__(16) unsigned long long g_table[TS];   // 4 MB dedupe hash
__device__ int      g_is64;
__device__ int      g_count[NN];          // distinct cells per row
__device__ float    g_deg[NN];
__device__ unsigned g_pos[TS];            // apos recorded by the claimant of a slot
__device__ __align__(16) uint2 g_cw[NN * PAD];   // 8 MB interleaved (col, w)
__device__ float2   g_tx1[NN * 32];
__device__ float2   g_ltx1[NN * 32];
__device__ int      g_nlist;
__device__ uint2    g_list[LISTCAP];      // (slot, edge idx) of duplicate-key inserts

// ---------------- kernels ----------------------------------------------------

// Clear table (16B stores) + counters; detect int32 vs int64 edge storage.
// g_cw is NOT cleared: slots beyond each row's count are never written, stay
// zero from static init, and (col=0, w=0) contributes exactly 0 in SpMM.
__global__ void k_clear(const unsigned* __restrict__ ei) {
    unsigned i = blockIdx.x * blockDim.x + threadIdx.x;       // 262144 threads
    ((ulonglong2*)g_table)[i] = make_ulonglong2(0ull, 0ull);  // 2 slots each
    if (i < NN) { g_count[i] = 0; g_deg[i] = 0.f; }
    if (i == 0) {
        g_nlist = 0;
        int all_zero = 1;
        for (int j = 1; j < 64; j += 2) all_zero &= (ei[j] == 0u);
        g_is64 = all_zero;   // int64 LE with values<2^31 => odd words zero
    }
}

// Insert: claimant of a cell takes a padded-CSR position and writes (col,w) +
// REDG degree. Duplicate-key edges go to a tiny fix list. atomicMax on
// (key+1)<<32|(i+1) keeps the highest edge idx = last-write-wins.
__global__ void k_insert(const unsigned* __restrict__ ei,
                         const float* __restrict__ ew,
                         const float* __restrict__ adw, int E) {
    int i = blockIdx.x * blockDim.x + threadIdx.x;
    if (i >= E) return;
    int is64 = g_is64;
    unsigned row = is64 ? ei[2 * i]       : ei[i];
    unsigned col = is64 ? ei[2 * (E + i)] : ei[E + i];
    float sig = 1.f / (1.f + expf(-adw[0]));
    float aw  = ew[i] * sig;
    unsigned key = (row << 13) | col;                         // < 2^26
    unsigned long long packed =
        ((unsigned long long)(key + 1u) << 32) | (unsigned)(i + 1);
    unsigned slot = ((key * 2654435761u) >> 12) & TMASK;
    while (true) {
        unsigned long long cur = g_table[slot];
        if (cur == 0ull) {
            unsigned long long old = atomicCAS(&g_table[slot], 0ull, packed);
            if (old == 0ull) {                                 // claimed this cell
                int pos = atomicAdd(&g_count[row], 1);
                if (pos < PAD) {
                    unsigned apos = (row << 7) + (unsigned)pos;
                    g_pos[slot] = apos;
                    g_cw[apos]  = make_uint2(col, __float_as_uint(aw));
                    atomicAdd(&g_deg[row], aw);                // REDG (no return)
                }
                return;
            }
            cur = old;
        }
        if ((cur >> 32) == (unsigned long long)(key + 1u)) {   // duplicate cell
            atomicMax(&g_table[slot], packed);
            int p = atomicAdd(&g_nlist, 1);
            if (p < LISTCAP) g_list[p] = make_uint2(slot, (unsigned)i);
            return;
        }
        slot = (slot + 1u) & TMASK;
    }
}

// Apply last-write-wins corrections for duplicate cells (few hundred entries).
__global__ void k_fix(const float* __restrict__ ew,
                      const float* __restrict__ adw) {
    int idx = blockIdx.x * blockDim.x + threadIdx.x;
    int n = g_nlist; if (n > LISTCAP) n = LISTCAP;
    if (idx >= n) return;
    unsigned slot = g_list[idx].x;
    unsigned i    = g_list[idx].y;
    unsigned long long cur = g_table[slot];
    if ((unsigned)cur != i + 1u) return;                       // not the winner
    unsigned apos = g_pos[slot];
    float sig = 1.f / (1.f + expf(-adw[0]));
    float aw  = ew[i] * sig;
    float old = __uint_as_float(g_cw[apos].y);
    g_cw[apos].y = __float_as_uint(aw);
    atomicAdd(&g_deg[apos >> 7], aw - old);
}

// Y = L X. Warp per row, float2 per lane. Edge list read via warp-uniform
// uint4 broadcast loads (2 edges/load, affine address, no cross-lane deps ->
// all list loads + gathers front-batched, MLP ~48).
// SCALE (spmm1 only): coalesced per-lane prologue folds dinv[col] into the
// stored weights; syncwarp + block fence makes them visible to the uniform
// re-loads (same SM, L1 hits).
template <bool SCALE>
__device__ __forceinline__ void spmm_body(const float2* __restrict__ X2,
                                          float2* __restrict__ Y2) {
    int gw = (blockIdx.x * blockDim.x + threadIdx.x) >> 5;
    if (gw >= NN) return;
    int lane = threadIdx.x & 31;
    int cnt = g_count[gw]; if (cnt > PAD) cnt = PAD;
    int base = gw << 7;

    if (SCALE) {
        for (int j = lane; j < cnt; j += 32) {                 // coalesced
            uint2 cw = g_cw[base + j];
            float w = __uint_as_float(cw.y) * rsqrtf(g_deg[cw.x] + 1.0f);
            g_cw[base + j].y = __float_as_uint(w);
        }
        __threadfence_block();
        __syncwarp();
    }

    const uint4* __restrict__ cw4 = (const uint4*)(g_cw + base);
    float ax = 0.f, ay = 0.f;
    for (int j = 0; j < cnt; j += 32) {                        // zero-padded chunks
        const uint4* p = cw4 + (j >> 1);
#pragma unroll
        for (int t = 0; t < 16; t++) {                         // 2 edges per load
            uint4 e = p[t];                                    // uniform broadcast
            float2 v0 = X2[e.x * 32 + lane];
            float2 v1 = X2[e.z * 32 + lane];
            float w0 = __uint_as_float(e.y), w1 = __uint_as_float(e.w);
            ax = fmaf(w0, v0.x, ax);  ay = fmaf(w0, v0.y, ay);
            ax = fmaf(w1, v1.x, ax);  ay = fmaf(w1, v1.y, ay);
        }
    }
    float di = rsqrtf(g_deg[gw] + 1.0f);
    float2 xs = X2[gw * 32 + lane];
    float2 r;
    r.x = xs.x - di * (ax + di * xs.x);
    r.y = xs.y - di * (ay + di * xs.y);
    Y2[gw * 32 + lane] = r;
}

__global__ void k_spmm1(const float2* __restrict__ X2) { spmm_body<true >(X2, g_tx1); }
__global__ void k_spmm2()                              { spmm_body<false>(g_tx1, g_ltx1); }

// out = x*W0 + Tx1*W1 + (2*LTx1 - x)*W2 + bias. 4 rows/warp, W in smem.
__global__ void k_out(const float* __restrict__ x,
                      const float* __restrict__ W,
                      const float* __restrict__ bias,
                      float* __restrict__ out) {
    __shared__ float2 sW[3 * 64 * 32];                         // 48 KB
    const float2* __restrict__ W2 = (const float2*)W;
    for (int j = threadIdx.x; j < 3 * 64 * 32; j += blockDim.x) sW[j] = W2[j];
    __syncthreads();

    int warp = threadIdx.x >> 5;
    int lane = threadIdx.x & 31;
    int row0 = blockIdx.x * 32 + warp * 4;

    const float2* __restrict__ X2 = (const float2*)x;
    float2* __restrict__ O2 = (float2*)out;

    float2 xv[4], t1[4], t2[4], acc[4];
#pragma unroll
    for (int r = 0; r < 4; r++) {
        int row = row0 + r;
        xv[r] = X2[row * 32 + lane];
        t1[r] = g_tx1[row * 32 + lane];
        float2 lv = g_ltx1[row * 32 + lane];
        t2[r].x = 2.f * lv.x - xv[r].x;
        t2[r].y = 2.f * lv.y - xv[r].y;
        acc[r].x = 0.f; acc[r].y = 0.f;
    }

#pragma unroll 8
    for (int kp = 0; kp < 32; kp++) {
        int k0 = 2 * kp, k1 = 2 * kp + 1;
        float2 w00 = sW[k0 * 32 + lane],        w01 = sW[k1 * 32 + lane];
        float2 w10 = sW[2048 + k0 * 32 + lane], w11 = sW[2048 + k1 * 32 + lane];
        float2 w20 = sW[4096 + k0 * 32 + lane], w21 = sW[4096 + k1 * 32 + lane];
#pragma unroll
        for (int r = 0; r < 4; r++) {
            float bx0 = __shfl_sync(0xffffffffu, xv[r].x, kp);
            float bx1 = __shfl_sync(0xffffffffu, xv[r].y, kp);
            float b10 = __shfl_sync(0xffffffffu, t1[r].x, kp);
            float b11 = __shfl_sync(0xffffffffu, t1[r].y, kp);
            float b20 = __shfl_sync(0xffffffffu, t2[r].x, kp);
            float b21 = __shfl_sync(0xffffffffu, t2[r].y, kp);
            acc[r].x = fmaf(bx0, w00.x, acc[r].x); acc[r].x = fmaf(bx1, w01.x, acc[r].x);
            acc[r].x = fmaf(b10, w10.x, acc[r].x); acc[r].x = fmaf(b11, w11.x, acc[r].x);
            acc[r].x = fmaf(b20, w20.x, acc[r].x); acc[r].x = fmaf(b21, w21.x, acc[r].x);
            acc[r].y = fmaf(bx0, w00.y, acc[r].y); acc[r].y = fmaf(bx1, w01.y, acc[r].y);
            acc[r].y = fmaf(b10, w10.y, acc[r].y); acc[r].y = fmaf(b11, w11.y, acc[r].y);
            acc[r].y = fmaf(b20, w20.y, acc[r].y); acc[r].y = fmaf(b21, w21.y, acc[r].y);
        }
    }

    float2 b2 = ((const float2*)bias)[lane];
#pragma unroll
    for (int r = 0; r < 4; r++) {
        float2 o; o.x = acc[r].x + b2.x; o.y = acc[r].y + b2.y;
        O2[(row0 + r) * 32 + lane] = o;
    }
}

// ---------------- launch -----------------------------------------------------

extern "C" void kernel_launch(void* const* d_in, const int* in_sizes, int n_in,
                              void* d_out, int out_size) {
    const float*    x    = (const float*)d_in[0];
    const unsigned* ei   = (const unsigned*)d_in[1];   // int32 OR int64 raw words
    const float*    ew   = (const float*)d_in[2];      // (E,)
    const float*    W    = (const float*)d_in[3];      // (3, 64, 64)
    const float*    adw  = (const float*)d_in[4];      // (1,)
    const float*    bias = (const float*)d_in[5];      // (64,)
    float*          out  = (float*)d_out;

    int E = in_sizes[2];
    if (E > EMAX) E = EMAX;   // fixed problem; defensive only
    int eb = (E + 255) / 256;

    k_clear <<<TS / 2 / 256, 256>>>(ei);               // 1024 blocks
    k_insert<<<eb, 256>>>(ei, ew, adw, E);
    k_fix   <<<LISTCAP / 256, 256>>>(ew, adw);
    k_spmm1 <<<NN * 32 / 256, 256>>>((const float2*)x); // Tx1 = L x (+ scale fold)
    k_spmm2 <<<NN * 32 / 256, 256>>>();                 // LTx1 = L Tx1
    k_out   <<<NN / 32, 256>>>(x, W, bias, out);
}

// round 10
// speedup vs baseline: 1.0639x; 1.0301x over previous
#include <cuda_runtime.h>
#include <stdint.h>
#include <math.h>

// Problem constants (fixed by the dataset).
#define NN      8192
#define CC      64
#define EMAX    262144
#define PAD     128                 // padded CSR row stride (mean deg 32)
#define TS      (1u << 19)          // hash slots (load factor ~0.5)
#define TMASK   (TS - 1u)
#define LISTCAP 16384

// ---------------- scratch (static device globals; no allocation) -------------
__device__ __align__(16) unsigned long long g_table[TS];   // 4 MB dedupe hash
__device__ int      g_is64;
__device__ int      g_count[NN];          // distinct cells per row
__device__ float    g_deg[NN];
__device__ unsigned g_pos[TS];            // apos recorded by the claimant of a slot
__device__ __align__(16) uint2 g_cw[NN * PAD];   // 8 MB interleaved (col, w)
__device__ float2   g_tx1[NN * 32];
__device__ float2   g_ltx1[NN * 32];
__device__ int      g_nlist;
__device__ uint2    g_list[LISTCAP];      // (slot, edge idx) of duplicate-key inserts

// ---------------- kernels ----------------------------------------------------

// Clear table (16B stores) + counters; detect int32 vs int64 edge storage.
// g_cw is NOT cleared: slots beyond each row's count are never written, stay
// zero from static init, and (col=0, w=0) contributes exactly 0 in SpMM.
__global__ void k_clear(const unsigned* __restrict__ ei) {
    unsigned i = blockIdx.x * blockDim.x + threadIdx.x;       // 262144 threads
    ((ulonglong2*)g_table)[i] = make_ulonglong2(0ull, 0ull);  // 2 slots each
    if (i < NN) { g_count[i] = 0; g_deg[i] = 0.f; }
    if (i == 0) {
        g_nlist = 0;
        int all_zero = 1;
        for (int j = 1; j < 64; j += 2) all_zero &= (ei[j] == 0u);
        g_is64 = all_zero;   // int64 LE with values<2^31 => odd words zero
    }
}

// Insert: claimant of a cell takes a padded-CSR position and writes (col,w) +
// REDG degree. Duplicate-key edges go to a tiny fix list. atomicMax on
// (key+1)<<32|(i+1) keeps the highest edge idx = last-write-wins.
__global__ void k_insert(const unsigned* __restrict__ ei,
                         const float* __restrict__ ew,
                         const float* __restrict__ adw, int E) {
    int i = blockIdx.x * blockDim.x + threadIdx.x;
    if (i >= E) return;
    unsigned row, col;
    if (g_is64) {                                 // coalesced 8B loads
        row = ((const uint2*)ei)[i].x;
        col = ((const uint2*)ei)[E + i].x;
    } else {
        row = ei[i];
        col = ei[E + i];
    }
    float sig = 1.f / (1.f + expf(-adw[0]));
    float aw  = ew[i] * sig;
    unsigned key = (row << 13) | col;                         // < 2^26
    unsigned long long packed =
        ((unsigned long long)(key + 1u) << 32) | (unsigned)(i + 1);
    unsigned slot = ((key * 2654435761u) >> 12) & TMASK;
    while (true) {
        unsigned long long cur = g_table[slot];
        if (cur == 0ull) {
            unsigned long long old = atomicCAS(&g_table[slot], 0ull, packed);
            if (old == 0ull) {                                 // claimed this cell
                int pos = atomicAdd(&g_count[row], 1);
                if (pos < PAD) {
                    unsigned apos = (row << 7) + (unsigned)pos;
                    g_pos[slot] = apos;
                    g_cw[apos]  = make_uint2(col, __float_as_uint(aw));
                    atomicAdd(&g_deg[row], aw);                // REDG (no return)
                }
                return;
            }
            cur = old;
        }
        if ((cur >> 32) == (unsigned long long)(key + 1u)) {   // duplicate cell
            atomicMax(&g_table[slot], packed);
            int p = atomicAdd(&g_nlist, 1);
            if (p < LISTCAP) g_list[p] = make_uint2(slot, (unsigned)i);
            return;
        }
        slot = (slot + 1u) & TMASK;
    }
}

// Apply last-write-wins corrections for duplicate cells (few hundred entries).
__global__ void k_fix(const float* __restrict__ ew,
                      const float* __restrict__ adw) {
    int idx = blockIdx.x * blockDim.x + threadIdx.x;
    int n = g_nlist; if (n > LISTCAP) n = LISTCAP;
    if (idx >= n) return;
    unsigned slot = g_list[idx].x;
    unsigned i    = g_list[idx].y;
    unsigned long long cur = g_table[slot];
    if ((unsigned)cur != i + 1u) return;                       // not the winner
    unsigned apos = g_pos[slot];
    float sig = 1.f / (1.f + expf(-adw[0]));
    float aw  = ew[i] * sig;
    float old = __uint_as_float(g_cw[apos].y);
    g_cw[apos].y = __float_as_uint(aw);
    atomicAdd(&g_deg[apos >> 7], aw - old);
}

// Y = L X. TWO rows per warp, interleaved -> two independent shfl/gather/FMA
// chains per warp (2x outstanding gathers). float2 per lane (64 features).
// Zero-padded fixed-32 inner loop: padding entries are (0,0), contribute 0.
// SCALE (spmm1): lane scales the element it loaded (register-resident for the
// shfl loop) and writes it back for spmm2.
template <bool SCALE>
__device__ __forceinline__ void spmm_body(const float2* __restrict__ X2,
                                          float2* __restrict__ Y2) {
    int gw = (blockIdx.x * blockDim.x + threadIdx.x) >> 5;     // 4096 warps
    int rowA = gw * 2, rowB = gw * 2 + 1;
    if (rowA >= NN) return;
    int lane = threadIdx.x & 31;
    int cntA = g_count[rowA]; if (cntA > PAD) cntA = PAD;
    int cntB = g_count[rowB]; if (cntB > PAD) cntB = PAD;
    int cmax = max(cntA, cntB);
    int baseA = rowA << 7, baseB = rowB << 7;

    float ax0 = 0.f, ay0 = 0.f, ax1 = 0.f, ay1 = 0.f;
    for (int j = 0; j < cmax; j += 32) {
        uint2 ea = g_cw[baseA + j + lane];                     // zero beyond cntA
        uint2 eb = g_cw[baseB + j + lane];
        int   ca = (int)ea.x;  float wa = __uint_as_float(ea.y);
        int   cb = (int)eb.x;  float wb = __uint_as_float(eb.y);
        if (SCALE) {
            wa *= rsqrtf(g_deg[ca] + 1.0f);
            wb *= rsqrtf(g_deg[cb] + 1.0f);
            g_cw[baseA + j + lane].y = __float_as_uint(wa);    // persist for spmm2
            g_cw[baseB + j + lane].y = __float_as_uint(wb);
        }
#pragma unroll
        for (int t = 0; t < 32; t++) {
            int   cca = __shfl_sync(0xffffffffu, ca, t);
            float wwa = __shfl_sync(0xffffffffu, wa, t);
            int   ccb = __shfl_sync(0xffffffffu, cb, t);
            float wwb = __shfl_sync(0xffffffffu, wb, t);
            float2 va = X2[cca * 32 + lane];
            float2 vb = X2[ccb * 32 + lane];
            ax0 = fmaf(wwa, va.x, ax0);  ay0 = fmaf(wwa, va.y, ay0);
            ax1 = fmaf(wwb, vb.x, ax1);  ay1 = fmaf(wwb, vb.y, ay1);
        }
    }
    float diA = rsqrtf(g_deg[rowA] + 1.0f);
    float diB = rsqrtf(g_deg[rowB] + 1.0f);
    float2 xa = X2[rowA * 32 + lane];
    float2 xb = X2[rowB * 32 + lane];
    Y2[rowA * 32 + lane] = make_float2(xa.x - diA * (ax0 + diA * xa.x),
                                       xa.y - diA * (ay0 + diA * xa.y));
    Y2[rowB * 32 + lane] = make_float2(xb.x - diB * (ax1 + diB * xb.x),
                                       xb.y - diB * (ay1 + diB * xb.y));
}

__global__ void k_spmm1(const float2* __restrict__ X2) { spmm_body<true >(X2, g_tx1); }
__global__ void k_spmm2()                              { spmm_body<false>(g_tx1, g_ltx1); }

// out = x*W0 + Tx1*W1 + (2*LTx1 - x)*W2 + bias. 4 rows/warp, W in smem.
__global__ void k_out(const float* __restrict__ x,
                      const float* __restrict__ W,
                      const float* __restrict__ bias,
                      float* __restrict__ out) {
    __shared__ float2 sW[3 * 64 * 32];                         // 48 KB
    const float2* __restrict__ W2 = (const float2*)W;
    for (int j = threadIdx.x; j < 3 * 64 * 32; j += blockDim.x) sW[j] = W2[j];
    __syncthreads();

    int warp = threadIdx.x >> 5;
    int lane = threadIdx.x & 31;
    int row0 = blockIdx.x * 32 + warp * 4;

    const float2* __restrict__ X2 = (const float2*)x;
    float2* __restrict__ O2 = (float2*)out;

    float2 xv[4], t1[4], t2[4], acc[4];
#pragma unroll
    for (int r = 0; r < 4; r++) {
        int row = row0 + r;
        xv[r] = X2[row * 32 + lane];
        t1[r] = g_tx1[row * 32 + lane];
        float2 lv = g_ltx1[row * 32 + lane];
        t2[r].x = 2.f * lv.x - xv[r].x;
        t2[r].y = 2.f * lv.y - xv[r].y;
        acc[r].x = 0.f; acc[r].y = 0.f;
    }

#pragma unroll 8
    for (int kp = 0; kp < 32; kp++) {
        int k0 = 2 * kp, k1 = 2 * kp + 1;
        float2 w00 = sW[k0 * 32 + lane],        w01 = sW[k1 * 32 + lane];
        float2 w10 = sW[2048 + k0 * 32 + lane], w11 = sW[2048 + k1 * 32 + lane];
        float2 w20 = sW[4096 + k0 * 32 + lane], w21 = sW[4096 + k1 * 32 + lane];
#pragma unroll
        for (int r = 0; r < 4; r++) {
            float bx0 = __shfl_sync(0xffffffffu, xv[r].x, kp);
            float bx1 = __shfl_sync(0xffffffffu, xv[r].y, kp);
            float b10 = __shfl_sync(0xffffffffu, t1[r].x, kp);
            float b11 = __shfl_sync(0xffffffffu, t1[r].y, kp);
            float b20 = __shfl_sync(0xffffffffu, t2[r].x, kp);
            float b21 = __shfl_sync(0xffffffffu, t2[r].y, kp);
            acc[r].x = fmaf(bx0, w00.x, acc[r].x); acc[r].x = fmaf(bx1, w01.x, acc[r].x);
            acc[r].x = fmaf(b10, w10.x, acc[r].x); acc[r].x = fmaf(b11, w11.x, acc[r].x);
            acc[r].x = fmaf(b20, w20.x, acc[r].x); acc[r].x = fmaf(b21, w21.x, acc[r].x);
            acc[r].y = fmaf(bx0, w00.y, acc[r].y); acc[r].y = fmaf(bx1, w01.y, acc[r].y);
            acc[r].y = fmaf(b10, w10.y, acc[r].y); acc[r].y = fmaf(b11, w11.y, acc[r].y);
            acc[r].y = fmaf(b20, w20.y, acc[r].y); acc[r].y = fmaf(b21, w21.y, acc[r].y);
        }
    }

    float2 b2 = ((const float2*)bias)[lane];
#pragma unroll
    for (int r = 0; r < 4; r++) {
        float2 o; o.x = acc[r].x + b2.x; o.y = acc[r].y + b2.y;
        O2[(row0 + r) * 32 + lane] = o;
    }
}

// ---------------- launch -----------------------------------------------------

extern "C" void kernel_launch(void* const* d_in, const int* in_sizes, int n_in,
                              void* d_out, int out_size) {
    const float*    x    = (const float*)d_in[0];
    const unsigned* ei   = (const unsigned*)d_in[1];   // int32 OR int64 raw words
    const float*    ew   = (const float*)d_in[2];      // (E,)
    const float*    W    = (const float*)d_in[3];      // (3, 64, 64)
    const float*    adw  = (const float*)d_in[4];      // (1,)
    const float*    bias = (const float*)d_in[5];      // (64,)
    float*          out  = (float*)d_out;

    int E = in_sizes[2];
    if (E > EMAX) E = EMAX;   // fixed problem; defensive only
    int eb = (E + 255) / 256;

    k_clear <<<TS / 2 / 256, 256>>>(ei);               // 1024 blocks
    k_insert<<<eb, 256>>>(ei, ew, adw, E);
    k_fix   <<<LISTCAP / 256, 256>>>(ew, adw);
    k_spmm1 <<<NN / 2 * 32 / 256, 256>>>((const float2*)x); // 512 blocks
    k_spmm2 <<<NN / 2 * 32 / 256, 256>>>();
    k_out   <<<NN / 32, 256>>>(x, W, bias, out);
}

// round 11
// speedup vs baseline: 1.2095x; 1.1368x over previous
#include <cuda_runtime.h>
#include <stdint.h>
#include <math.h>

// Problem constants (fixed by the dataset).
#define NN      8192
#define CC      64
#define EMAX    262144
#define PAD     128                 // padded CSR row stride (mean deg 32)
#define TS      (1u << 19)          // hash slots (load factor ~0.5)
#define TMASK   (TS - 1u)
#define LISTCAP 16384

// ---------------- scratch (static device globals; no allocation) -------------
__device__ __align__(16) unsigned long long g_table[TS];   // 4 MB dedupe hash
__device__ int      g_is64;
__device__ int      g_count[NN];          // distinct cells per row
__device__ float    g_deg[NN];
__device__ unsigned g_pos[TS];            // apos recorded by the claimant of a slot
__device__ __align__(16) uint2 g_cw[NN * PAD];   // 8 MB interleaved (col, w)
__device__ float2   g_tx1[NN * 32];
__device__ float2   g_ltx1[NN * 32];
__device__ int      g_nlist;
__device__ uint2    g_list[LISTCAP];      // (slot, edge idx) of duplicate-key inserts

// ---------------- kernels ----------------------------------------------------

// Clear table (16B stores) + counters; detect int32 vs int64 edge storage.
__global__ void k_clear(const unsigned* __restrict__ ei) {
    unsigned i = blockIdx.x * blockDim.x + threadIdx.x;       // 262144 threads
    ((ulonglong2*)g_table)[i] = make_ulonglong2(0ull, 0ull);  // 2 slots each
    if (i < NN) { g_count[i] = 0; g_deg[i] = 0.f; }
    if (i == 0) {
        g_nlist = 0;
        int all_zero = 1;
        for (int j = 1; j < 64; j += 2) all_zero &= (ei[j] == 0u);
        g_is64 = all_zero;   // int64 LE with values<2^31 => odd words zero
    }
}

// Insert: claimant of a cell takes a padded-CSR position and writes (col,w) +
// REDG degree. Duplicate-key edges go to a tiny fix list. atomicMax on
// (key+1)<<32|(i+1) keeps the highest edge idx = last-write-wins.
__global__ void k_insert(const unsigned* __restrict__ ei,
                         const float* __restrict__ ew,
                         const float* __restrict__ adw, int E) {
    int i = blockIdx.x * blockDim.x + threadIdx.x;
    if (i >= E) return;
    unsigned row, col;
    if (g_is64) {                                 // coalesced 8B loads
        row = ((const uint2*)ei)[i].x;
        col = ((const uint2*)ei)[E + i].x;
    } else {
        row = ei[i];
        col = ei[E + i];
    }
    float sig = 1.f / (1.f + expf(-adw[0]));
    float aw  = ew[i] * sig;
    unsigned key = (row << 13) | col;                         // < 2^26
    unsigned long long packed =
        ((unsigned long long)(key + 1u) << 32) | (unsigned)(i + 1);
    unsigned slot = ((key * 2654435761u) >> 12) & TMASK;
    while (true) {
        unsigned long long cur = g_table[slot];
        if (cur == 0ull) {
            unsigned long long old = atomicCAS(&g_table[slot], 0ull, packed);
            if (old == 0ull) {                                 // claimed this cell
                int pos = atomicAdd(&g_count[row], 1);
                if (pos < PAD) {
                    unsigned apos = (row << 7) + (unsigned)pos;
                    g_pos[slot] = apos;
                    g_cw[apos]  = make_uint2(col, __float_as_uint(aw));
                    atomicAdd(&g_deg[row], aw);                // REDG (no return)
                }
                return;
            }
            cur = old;
        }
        if ((cur >> 32) == (unsigned long long)(key + 1u)) {   // duplicate cell
            atomicMax(&g_table[slot], packed);
            int p = atomicAdd(&g_nlist, 1);
            if (p < LISTCAP) g_list[p] = make_uint2(slot, (unsigned)i);
            return;
        }
        slot = (slot + 1u) & TMASK;
    }
}

// Apply last-write-wins corrections for duplicate cells (few hundred entries).
__global__ void k_fix(const float* __restrict__ ew,
                      const float* __restrict__ adw) {
    int idx = blockIdx.x * blockDim.x + threadIdx.x;
    int n = g_nlist; if (n > LISTCAP) n = LISTCAP;
    if (idx >= n) return;
    unsigned slot = g_list[idx].x;
    unsigned i    = g_list[idx].y;
    unsigned long long cur = g_table[slot];
    if ((unsigned)cur != i + 1u) return;                       // not the winner
    unsigned apos = g_pos[slot];
    float sig = 1.f / (1.f + expf(-adw[0]));
    float aw  = ew[i] * sig;
    float old = __uint_as_float(g_cw[apos].y);
    g_cw[apos].y = __float_as_uint(aw);
    atomicAdd(&g_deg[apos >> 7], aw - old);
}

// Y = L X. Warp per row, float2 per lane (64 features). Edge-EXACT dynamic
// loop (no chunk padding — Poisson(32) rows make fixed-32 padding +46% work).
// Row's edge list staged to smem once (coalesced), then broadcast via LDS.64
// (uniform, conflict-free): per edge = LDS.64 + IMAD + LDG.64 + 2 FMA,
// replacing the two-SHFL broadcast of the R5 form.
// SCALE (spmm1): dinv[col] folded during staging; written back for spmm2.
template <bool SCALE>
__device__ __forceinline__ void spmm_body(const float2* __restrict__ X2,
                                          float2* __restrict__ Y2) {
    __shared__ uint2 s_edges[8][PAD];                          // 8 KB (8 warps)
    int gw = (blockIdx.x * blockDim.x + threadIdx.x) >> 5;
    if (gw >= NN) return;
    int lane = threadIdx.x & 31;
    uint2* srow = s_edges[(threadIdx.x >> 5) & 7];
    int cnt = g_count[gw]; if (cnt > PAD) cnt = PAD;
    int base = gw << 7;

    for (int j = lane; j < cnt; j += 32) {                     // coalesced stage
        uint2 cw = g_cw[base + j];
        if (SCALE) {
            float w = __uint_as_float(cw.y) * rsqrtf(g_deg[cw.x] + 1.0f);
            cw.y = __float_as_uint(w);
            g_cw[base + j] = cw;                               // persist for spmm2
        }
        srow[j] = cw;
    }
    __syncwarp();

    float ax = 0.f, ay = 0.f;
#pragma unroll 4
    for (int t = 0; t < cnt; t++) {
        uint2 e = srow[t];                                     // LDS.64 broadcast
        float w = __uint_as_float(e.y);
        float2 xv = X2[e.x * 32 + lane];
        ax = fmaf(w, xv.x, ax);
        ay = fmaf(w, xv.y, ay);
    }

    float di = rsqrtf(g_deg[gw] + 1.0f);
    float2 xs = X2[gw * 32 + lane];
    float2 r;
    r.x = xs.x - di * (ax + di * xs.x);
    r.y = xs.y - di * (ay + di * xs.y);
    Y2[gw * 32 + lane] = r;
}

__global__ void k_spmm1(const float2* __restrict__ X2) { spmm_body<true >(X2, g_tx1); }
__global__ void k_spmm2()                              { spmm_body<false>(g_tx1, g_ltx1); }

// out = x*W0 + Tx1*W1 + (2*LTx1 - x)*W2 + bias. 4 rows/warp, W in smem.
__global__ void k_out(const float* __restrict__ x,
                      const float* __restrict__ W,
                      const float* __restrict__ bias,
                      float* __restrict__ out) {
    __shared__ float2 sW[3 * 64 * 32];                         // 48 KB
    const float2* __restrict__ W2 = (const float2*)W;
    for (int j = threadIdx.x; j < 3 * 64 * 32; j += blockDim.x) sW[j] = W2[j];
    __syncthreads();

    int warp = threadIdx.x >> 5;
    int lane = threadIdx.x & 31;
    int row0 = blockIdx.x * 32 + warp * 4;

    const float2* __restrict__ X2 = (const float2*)x;
    float2* __restrict__ O2 = (float2*)out;

    float2 xv[4], t1[4], t2[4], acc[4];
#pragma unroll
    for (int r = 0; r < 4; r++) {
        int row = row0 + r;
        xv[r] = X2[row * 32 + lane];
        t1[r] = g_tx1[row * 32 + lane];
        float2 lv = g_ltx1[row * 32 + lane];
        t2[r].x = 2.f * lv.x - xv[r].x;
        t2[r].y = 2.f * lv.y - xv[r].y;
        acc[r].x = 0.f; acc[r].y = 0.f;
    }

#pragma unroll 8
    for (int kp = 0; kp < 32; kp++) {
        int k0 = 2 * kp, k1 = 2 * kp + 1;
        float2 w00 = sW[k0 * 32 + lane],        w01 = sW[k1 * 32 + lane];
        float2 w10 = sW[2048 + k0 * 32 + lane], w11 = sW[2048 + k1 * 32 + lane];
        float2 w20 = sW[4096 + k0 * 32 + lane], w21 = sW[4096 + k1 * 32 + lane];
#pragma unroll
        for (int r = 0; r < 4; r++) {
            float bx0 = __shfl_sync(0xffffffffu, xv[r].x, kp);
            float bx1 = __shfl_sync(0xffffffffu, xv[r].y, kp);
            float b10 = __shfl_sync(0xffffffffu, t1[r].x, kp);
            float b11 = __shfl_sync(0xffffffffu, t1[r].y, kp);
            float b20 = __shfl_sync(0xffffffffu, t2[r].x, kp);
            float b21 = __shfl_sync(0xffffffffu, t2[r].y, kp);
            acc[r].x = fmaf(bx0, w00.x, acc[r].x); acc[r].x = fmaf(bx1, w01.x, acc[r].x);
            acc[r].x = fmaf(b10, w10.x, acc[r].x); acc[r].x = fmaf(b11, w11.x, acc[r].x);
            acc[r].x = fmaf(b20, w20.x, acc[r].x); acc[r].x = fmaf(b21, w21.x, acc[r].x);
            acc[r].y = fmaf(bx0, w00.y, acc[r].y); acc[r].y = fmaf(bx1, w01.y, acc[r].y);
            acc[r].y = fmaf(b10, w10.y, acc[r].y); acc[r].y = fmaf(b11, w11.y, acc[r].y);
            acc[r].y = fmaf(b20, w20.y, acc[r].y); acc[r].y = fmaf(b21, w21.y, acc[r].y);
        }
    }

    float2 b2 = ((const float2*)bias)[lane];
#pragma unroll
    for (int r = 0; r < 4; r++) {
        float2 o; o.x = acc[r].x + b2.x; o.y = acc[r].y + b2.y;
        O2[(row0 + r) * 32 + lane] = o;
    }
}

// ---------------- launch -----------------------------------------------------

extern "C" void kernel_launch(void* const* d_in, const int* in_sizes, int n_in,
                              void* d_out, int out_size) {
    const float*    x    = (const float*)d_in[0];
    const unsigned* ei   = (const unsigned*)d_in[1];   // int32 OR int64 raw words
    const float*    ew   = (const float*)d_in[2];      // (E,)
    const float*    W    = (const float*)d_in[3];      // (3, 64, 64)
    const float*    adw  = (const float*)d_in[4];      // (1,)
    const float*    bias = (const float*)d_in[5];      // (64,)
    float*          out  = (float*)d_out;

    int E = in_sizes[2];
    if (E > EMAX) E = EMAX;   // fixed problem; defensive only
    int eb = (E + 255) / 256;

    k_clear <<<TS / 2 / 256, 256>>>(ei);               // 1024 blocks
    k_insert<<<eb, 256>>>(ei, ew, adw, E);
    k_fix   <<<LISTCAP / 256, 256>>>(ew, adw);
    k_spmm1 <<<NN * 32 / 256, 256>>>((const float2*)x); // Tx1 = L x (+ scale fold)
    k_spmm2 <<<NN * 32 / 256, 256>>>();                 // LTx1 = L Tx1
    k_out   <<<NN / 32, 256>>>(x, W, bias, out);
}